// round 8
// baseline (speedup 1.0000x reference)
#include <cuda_runtime.h>
#include <cstdint>

// Problem shapes (fixed by the dataset)
#define BB 64
#define QQ 512
#define CC 128
#define PP 2048
#define GG 256

// Tiling
#define BM 64          // Q tile (M)
#define BK 32          // persons per chunk (K of one fp8 MMA)
#define NKC (PP / BK)  // 64 chunks
#define STAGES 8       // SMEM ring depth
#define NTH 512        // 8 consumer warps + 8 producer warps (4 groups x 2)

// Fragment-native fp8 stage layout: A [8 kwords][A_ROWW], B [8 kwords][B_ROWW]
// pitches mod 32 == 8 -> conflict-free LDS.32 / STS.32 (verified bank maps)
#define A_ROWW 72                            // words: 64 q + 8 pad
#define B_ROWW 264                           // words: 256 g + 8 pad
#define A_WORDS (8 * A_ROWW)                 // 576
#define STAGE_WORDS (8 * (A_ROWW + B_ROWW))  // 2688 words = 10752 B
#define SMEM_DYN (STAGES * STAGE_WORDS * 4)  // 86016 B

#define L_PITCH 133  // fp32 logits epilogue pitch (odd -> gather-friendly)

__device__ __forceinline__ float softplus_f(float x) {
    return fmaxf(x, 0.0f) + __logf(1.0f + __expf(-fabsf(x)));
}

// ---------------------------------------------------------------------------
// PTX helpers
// ---------------------------------------------------------------------------
__device__ __forceinline__ uint32_t smem_u32(const void* p) {
    return (uint32_t)__cvta_generic_to_shared(p);
}

#define MBARRIER_INIT(addr, count)                                 \
    asm volatile("mbarrier.init.shared.b64 [%0], %1;" ::"r"(addr), \
                 "r"((uint32_t)(count))                            \
                 : "memory")

#define MBARRIER_ARRIVE(addr)                                      \
    asm volatile("mbarrier.arrive.shared.b64 _, [%0];" ::"r"(addr) \
                 : "memory")

#define MBARRIER_WAIT_PARITY(mbar_addr, phase_parity)                          \
    do {                                                                       \
        uint32_t _mbar = (uint32_t)(mbar_addr);                                \
        uint32_t _parity = (uint32_t)(phase_parity);                           \
        uint32_t _done;                                                        \
        asm volatile(                                                          \
            "{\n\t"                                                            \
            ".reg .pred p;\n\t"                                                \
            "mbarrier.try_wait.parity.acquire.cta.shared::cta.b64 p, [%1], "   \
            "%2;\n\t"                                                          \
            "selp.b32 %0, 1, 0, p;\n\t"                                        \
            "}"                                                                \
            : "=r"(_done)                                                      \
            : "r"(_mbar), "r"(_parity)                                         \
            : "memory");                                                       \
        if (!_done) {                                                          \
            asm volatile(                                                      \
                "{\n\t"                                                        \
                ".reg .pred P1;\n\t"                                           \
                "WAIT_LOOP_%=:\n\t"                                            \
                "mbarrier.try_wait.parity.acquire.cta.shared::cta.b64 P1, "    \
                "[%0], %1, 0x989680;\n\t"                                      \
                "@P1 bra.uni WAIT_DONE_%=;\n\t"                                \
                "bra.uni WAIT_LOOP_%=;\n\t"                                    \
                "WAIT_DONE_%=:\n\t"                                            \
                "}" ::"r"(_mbar),                                              \
                "r"(_parity)                                                   \
                : "memory");                                                   \
        }                                                                      \
    } while (0)

// pack 4 fp32 -> 4 e4m3 bytes, byte0 = f0 .. byte3 = f3
__device__ __forceinline__ uint32_t pack_e4m3(float f0, float f1, float f2,
                                              float f3) {
    unsigned short lo, hi;
    asm("cvt.rn.satfinite.e4m3x2.f32 %0, %1, %2;" : "=h"(lo) : "f"(f1), "f"(f0));
    asm("cvt.rn.satfinite.e4m3x2.f32 %0, %1, %2;" : "=h"(hi) : "f"(f3), "f"(f2));
    return (uint32_t)lo | ((uint32_t)hi << 16);
}

// 4x4 byte transpose across a quad: in lane r, bytes c = col c of row r;
// out lane r, bytes b = row b of col r. Verified mapping for all 4 lanes.
__device__ __forceinline__ uint32_t transpose4(uint32_t w, int r) {
    uint32_t a = __shfl_xor_sync(0xffffffffu, w, 1);
    uint32_t bb = __shfl_xor_sync(0xffffffffu, w, 2);
    uint32_t c = __shfl_xor_sync(0xffffffffu, w, 3);
    uint32_t sel_t = (r & 1) ? (((uint32_t)r << 4) | (uint32_t)(4 + r))
                             : (((uint32_t)(4 + r) << 4) | (uint32_t)r);
    uint32_t sel_o = (r & 2) ? 0x1054u : 0x5410u;
    uint32_t t0 = __byte_perm(w, a, sel_t);
    uint32_t t1 = __byte_perm(bb, c, sel_t);
    return __byte_perm(t0, t1, sel_o);
}

// fp8 MMA: D(16x8,f32) += A(16x32,e4m3) * B(32x8,e4m3)  (sm_89 baseline op)
__device__ __forceinline__ void mma_e4m3(float* d, const uint32_t* a,
                                         const uint32_t* b) {
    asm volatile(
        "mma.sync.aligned.m16n8k32.row.col.f32.e4m3.e4m3.f32 "
        "{%0,%1,%2,%3}, {%4,%5,%6,%7}, {%8,%9}, {%0,%1,%2,%3};"
        : "+f"(d[0]), "+f"(d[1]), "+f"(d[2]), "+f"(d[3])
        : "r"(a[0]), "r"(a[1]), "r"(a[2]), "r"(a[3]), "r"(b[0]), "r"(b[1]));
}

// ---------------------------------------------------------------------------
// Single fused kernel: fp8 GEMM + softplus(attw) + softplus(logits) + gather
// ---------------------------------------------------------------------------
extern "C" __global__ void __launch_bounds__(NTH, 1)
cost_kernel(const float* __restrict__ logits, const float* __restrict__ attw,
            const float* __restrict__ onehot, const int* __restrict__ ids,
            float* __restrict__ out) {
    extern __shared__ __align__(16) char dynsmem[];
    uint32_t* dynw = reinterpret_cast<uint32_t*>(dynsmem);

    __shared__ alignas(8) unsigned long long bar_full[STAGES];
    __shared__ alignas(8) unsigned long long bar_empty[STAGES];
    __shared__ float s_sp[BM];  // sum_p softplus(attw[:,q])
    __shared__ float s_sa[BM];  // sum_c softplus(logits[q,:])
    __shared__ int s_ids[GG];

    const int tid = threadIdx.x;
    const int lane = tid & 31;
    const int warp = tid >> 5;
    const int q0 = blockIdx.x * BM;
    const int b = blockIdx.y;

    if (tid < BM) s_sp[tid] = 0.0f;
    if (tid == 0) {
#pragma unroll
        for (int s = 0; s < STAGES; s++) {
            MBARRIER_INIT(smem_u32(&bar_full[s]), 64);  // one producer group
            MBARRIER_INIT(smem_u32(&bar_empty[s]), 8);  // 8 consumer warps
        }
    }
    __syncthreads();

    // accumulators live in consumer warps only
    float acc[2][8][4];
    const int wm = warp >> 2;  // 0..1 (consumers)
    const int wn = warp & 3;   // 0..3
    const int g = lane >> 2;   // groupID 0..7
    const int tig = lane & 3;  // thread-in-group

    if (warp < 8) {
        // ===================== CONSUMERS (warps 0..7) ======================
#pragma unroll
        for (int i = 0; i < 2; i++)
#pragma unroll
            for (int j = 0; j < 8; j++)
#pragma unroll
                for (int k = 0; k < 4; k++) acc[i][j][k] = 0.0f;

        for (int kc = 0; kc < NKC; ++kc) {
            const int st = kc & (STAGES - 1);
            MBARRIER_WAIT_PARITY(smem_u32(&bar_full[st]), (kc >> 3) & 1);

            const uint32_t* Aw = dynw + (size_t)st * STAGE_WORDS;
            const uint32_t* Bw = Aw + A_WORDS;

            // A fragments: a0=[kw=tig][m], a1=[tig][m+8], a2/a3 at kw=tig+4
            uint32_t aF[2][4];
#pragma unroll
            for (int mt = 0; mt < 2; mt++) {
                const uint32_t* plo = Aw + tig * A_ROWW + wm * 32 + mt * 16 + g;
                const uint32_t* phi = plo + 4 * A_ROWW;
                aF[mt][0] = plo[0];
                aF[mt][1] = plo[8];
                aF[mt][2] = phi[0];
                aF[mt][3] = phi[8];
            }
            // B fragments: b0=[kw=tig][n], b1=[kw=tig+4][n]
            uint32_t bF[8][2];
#pragma unroll
            for (int nt = 0; nt < 8; nt++) {
                const uint32_t* pb = Bw + tig * B_ROWW + wn * 64 + nt * 8 + g;
                bF[nt][0] = pb[0];
                bF[nt][1] = pb[4 * B_ROWW];
            }
#pragma unroll
            for (int mt = 0; mt < 2; mt++)
#pragma unroll
                for (int nt = 0; nt < 8; nt++)
                    mma_e4m3(acc[mt][nt], aF[mt], bF[nt]);

            __syncwarp();
            if (lane == 0) MBARRIER_ARRIVE(smem_u32(&bar_empty[st]));
        }
    } else {
        // ===================== PRODUCERS (warps 8..15) =====================
        const int pg = tid - 256;    // 0..255
        const int group = pg >> 6;   // 0..3 ; handles kc % 4 == group
        const int pt = pg & 63;      // 0..63 within group
        const int qd = pt >> 2;      // quad 0..15
        const int r = pt & 3;        // lane within quad

        const float* aG = attw + (size_t)b * PP * QQ;
        const float4* bG =
            reinterpret_cast<const float4*>(onehot + (size_t)b * PP * GG);

        float sp_loc[4] = {0.f, 0.f, 0.f, 0.f};

        for (int t = 0; t < NKC / 4; ++t) {
            const int kc = group + 4 * t;
            const int st = kc & (STAGES - 1);
            const int p0 = kc * BK;
            uint32_t* Aw = dynw + (size_t)st * STAGE_WORDS;
            uint32_t* Bw = Aw + A_WORDS;

            // ---- batched global loads (A tile + B block 0) ----
            float4 av[8];
#pragma unroll
            for (int i = 0; i < 8; i++) {
                const float4* ap = reinterpret_cast<const float4*>(
                    aG + (size_t)(p0 + 4 * i + r) * QQ + q0);
                av[i] = ap[qd];
            }
            float4 bv[8];
#pragma unroll
            for (int j = 0; j < 8; j++)
                bv[j] = bG[(size_t)(p0 + 4 * (j >> 2) + r) * (GG / 4) + qd +
                           16 * (j & 3)];

            // ---- A: softplus + pack + transpose (register-only, pre-wait)
            uint32_t aw[8];
#pragma unroll
            for (int i = 0; i < 8; i++) {
                sp_loc[0] += softplus_f(av[i].x);
                sp_loc[1] += softplus_f(av[i].y);
                sp_loc[2] += softplus_f(av[i].z);
                sp_loc[3] += softplus_f(av[i].w);
                uint32_t pk = pack_e4m3(av[i].x, av[i].y, av[i].z, av[i].w);
                aw[i] = transpose4(pk, r);
            }

            // wait until consumers released this stage
            MBARRIER_WAIT_PARITY(smem_u32(&bar_empty[st]), ((kc >> 3) + 1) & 1);

            // ---- A STS: word [kw=i][q = qd*4 + r]
#pragma unroll
            for (int i = 0; i < 8; i++) Aw[i * A_ROWW + qd * 4 + r] = aw[i];

            // ---- B: 4 blocks of 8, double-buffered loads ----
#pragma unroll
            for (int blk = 0; blk < 4; blk++) {
                float4 nb[8];
                if (blk < 3) {
#pragma unroll
                    for (int j = 0; j < 8; j++)
                        nb[j] = bG[(size_t)(p0 + 8 * (blk + 1) + 4 * (j >> 2) +
                                            r) *
                                       (GG / 4) +
                                   qd + 16 * (j & 3)];
                }
#pragma unroll
                for (int j = 0; j < 8; j++) {
                    uint32_t pk = pack_e4m3(bv[j].x, bv[j].y, bv[j].z, bv[j].w);
                    uint32_t wv = transpose4(pk, r);
                    const int kw = 2 * blk + (j >> 2);
                    const int g4 = qd + 16 * (j & 3);
                    Bw[kw * B_ROWW + g4 * 4 + r] = wv;
                }
                if (blk < 3) {
#pragma unroll
                    for (int j = 0; j < 8; j++) bv[j] = nb[j];
                }
            }
            // release semantics of arrive order the STS before consumers' acquire
            MBARRIER_ARRIVE(smem_u32(&bar_full[st]));
        }

        // softplus(attw) reduction: thread owns q = qd*4 + j (16 contributors/q)
#pragma unroll
        for (int j = 0; j < 4; j++) atomicAdd(&s_sp[qd * 4 + j], sp_loc[j]);
    }

    // ============================ EPILOGUE =============================
    __syncthreads();  // mainloop done; ring SMEM reusable

    // stage logits fp32 (pitch 133) + ids
    {
        float* slog = reinterpret_cast<float*>(dynsmem);
        const float4* lG = reinterpret_cast<const float4*>(
            logits + (size_t)(b * QQ + q0) * CC);
#pragma unroll
        for (int i = 0; i < 4; i++) {
            int idx = tid + i * NTH;  // 0..2047 exactly covers 64x128
            float4 v = lG[idx];
            int m = idx >> 5;
            int fc = (idx & 31) * 4;
            float* dst = slog + m * L_PITCH + fc;
            dst[0] = v.x;
            dst[1] = v.y;
            dst[2] = v.z;
            dst[3] = v.w;
        }
        if (tid < GG) s_ids[tid] = ids[b * GG + tid];
    }
    __syncthreads();

    // SA: sum_c softplus(logits[m,:]) — 8 threads per row
    {
        const int row = tid >> 3;
        const int cb = tid & 7;
        const float* lr = reinterpret_cast<const float*>(dynsmem) + row * L_PITCH;
        float ss = 0.f;
#pragma unroll
        for (int k = 0; k < 16; k++) ss += softplus_f(lr[cb + 8 * k]);
        ss += __shfl_xor_sync(0xffffffffu, ss, 1);
        ss += __shfl_xor_sync(0xffffffffu, ss, 2);
        ss += __shfl_xor_sync(0xffffffffu, ss, 4);
        if (cb == 0) s_sa[row] = ss;
    }
    __syncthreads();

    if (warp < 8) {
        // output: cost = s_sp/P + s_sa/C - acc/P - gathered_logit/C
        const float inv_p = 1.0f / PP;
        const float inv_c = 1.0f / CC;
        const float* slog = reinterpret_cast<const float*>(dynsmem);
#pragma unroll
        for (int mt = 0; mt < 2; mt++) {
#pragma unroll
            for (int rr = 0; rr < 2; rr++) {
                const int m = wm * 32 + mt * 16 + g + rr * 8;
                const float Sm = s_sp[m] * inv_p + s_sa[m] * inv_c;
                float* orow = out + (size_t)(b * QQ + q0 + m) * GG;
                const float* lrow = slog + m * L_PITCH;
#pragma unroll
                for (int nt = 0; nt < 8; nt++) {
                    const int n = wn * 64 + nt * 8 + 2 * tig;
                    const float d0 = acc[mt][nt][rr * 2 + 0];
                    const float d1 = acc[mt][nt][rr * 2 + 1];
                    float2 o;
                    o.x = Sm - d0 * inv_p - lrow[s_ids[n]] * inv_c;
                    o.y = Sm - d1 * inv_p - lrow[s_ids[n + 1]] * inv_c;
                    *reinterpret_cast<float2*>(orow + n) = o;
                }
            }
        }
    }
}

// ---------------------------------------------------------------------------
extern "C" void kernel_launch(void* const* d_in, const int* in_sizes, int n_in,
                              void* d_out, int out_size) {
    const float* logits = (const float*)d_in[0];  // [B,Q,C]
    const float* attw = (const float*)d_in[1];    // [B,P,Q]
    const float* onehot = (const float*)d_in[2];  // [B,P,G]
    const int* ids = (const int*)d_in[3];         // [B,G]
    float* out = (float*)d_out;                   // [B,Q,G]

    cudaFuncSetAttribute(cost_kernel,
                         cudaFuncAttributeMaxDynamicSharedMemorySize, SMEM_DYN);

    dim3 grid(QQ / BM, BB);  // 8 x 64 = 512 CTAs
    cost_kernel<<<grid, NTH, SMEM_DYN>>>(logits, attw, onehot, ids, out);
}

// round 9
// speedup vs baseline: 1.9095x; 1.9095x over previous
#include <cuda_runtime.h>
#include <cstdint>

// Problem shapes (fixed by the dataset)
#define BB 64
#define QQ 512
#define CC 128
#define PP 2048
#define GG 256

// Tiling
#define BM 64          // Q tile (M)
#define BK 32          // persons per chunk (K of one fp8 MMA)
#define NKC (PP / BK)  // 64 chunks
#define STAGES 8       // SMEM ring depth
#define NTH 512        // 8 consumer warps + 8 producer warps (4 groups x 2)

// Fragment-native fp8 stage layout: A [8 kwords][A_ROWW], B [8 kwords][B_ROWW]
// pitches mod 32 == 8 -> conflict-free LDS.32 / STS (verified bank maps)
#define A_ROWW 72                            // words: 64 q + 8 pad
#define B_ROWW 264                           // words: 256 g + 8 pad
#define A_WORDS (8 * A_ROWW)                 // 576
#define STAGE_WORDS (8 * (A_ROWW + B_ROWW))  // 2688 words = 10752 B
#define SMEM_DYN (STAGES * STAGE_WORDS * 4)  // 86016 B

#define L_PITCH 133  // fp32 logits epilogue pitch

__device__ __forceinline__ float softplus_f(float x) {
    return fmaxf(x, 0.0f) + __logf(1.0f + __expf(-fabsf(x)));
}

// ---------------------------------------------------------------------------
// PTX helpers
// ---------------------------------------------------------------------------
__device__ __forceinline__ uint32_t smem_u32(const void* p) {
    return (uint32_t)__cvta_generic_to_shared(p);
}

#define MBARRIER_INIT(addr, count)                                 \
    asm volatile("mbarrier.init.shared.b64 [%0], %1;" ::"r"(addr), \
                 "r"((uint32_t)(count))                            \
                 : "memory")

#define MBARRIER_ARRIVE(addr)                                      \
    asm volatile("mbarrier.arrive.shared.b64 _, [%0];" ::"r"(addr) \
                 : "memory")

#define MBARRIER_WAIT_PARITY(mbar_addr, phase_parity)                          \
    do {                                                                       \
        uint32_t _mbar = (uint32_t)(mbar_addr);                                \
        uint32_t _parity = (uint32_t)(phase_parity);                           \
        uint32_t _done;                                                        \
        asm volatile(                                                          \
            "{\n\t"                                                            \
            ".reg .pred p;\n\t"                                                \
            "mbarrier.try_wait.parity.acquire.cta.shared::cta.b64 p, [%1], "   \
            "%2;\n\t"                                                          \
            "selp.b32 %0, 1, 0, p;\n\t"                                        \
            "}"                                                                \
            : "=r"(_done)                                                      \
            : "r"(_mbar), "r"(_parity)                                         \
            : "memory");                                                       \
        if (!_done) {                                                          \
            asm volatile(                                                      \
                "{\n\t"                                                        \
                ".reg .pred P1;\n\t"                                           \
                "WAIT_LOOP_%=:\n\t"                                            \
                "mbarrier.try_wait.parity.acquire.cta.shared::cta.b64 P1, "    \
                "[%0], %1, 0x989680;\n\t"                                      \
                "@P1 bra.uni WAIT_DONE_%=;\n\t"                                \
                "bra.uni WAIT_LOOP_%=;\n\t"                                    \
                "WAIT_DONE_%=:\n\t"                                            \
                "}" ::"r"(_mbar),                                              \
                "r"(_parity)                                                   \
                : "memory");                                                   \
        }                                                                      \
    } while (0)

// pack 4 fp32 -> 4 e4m3 bytes, byte0 = f0 .. byte3 = f3
__device__ __forceinline__ uint32_t pack_e4m3(float f0, float f1, float f2,
                                              float f3) {
    unsigned short lo, hi;
    asm("cvt.rn.satfinite.e4m3x2.f32 %0, %1, %2;" : "=h"(lo) : "f"(f1), "f"(f0));
    asm("cvt.rn.satfinite.e4m3x2.f32 %0, %1, %2;" : "=h"(hi) : "f"(f3), "f"(f2));
    return (uint32_t)lo | ((uint32_t)hi << 16);
}

#define STS128(addr, w0, w1, w2, w3)                                       \
    asm volatile("st.shared.v4.b32 [%0], {%1, %2, %3, %4};" ::"r"(addr),   \
                 "r"(w0), "r"(w1), "r"(w2), "r"(w3)                        \
                 : "memory")

// fp8 MMA: D(16x8,f32) += A(16x32,e4m3) * B(32x8,e4m3)  (sm_89 baseline op)
__device__ __forceinline__ void mma_e4m3(float* d, const uint32_t* a,
                                         const uint32_t* b) {
    asm volatile(
        "mma.sync.aligned.m16n8k32.row.col.f32.e4m3.e4m3.f32 "
        "{%0,%1,%2,%3}, {%4,%5,%6,%7}, {%8,%9}, {%0,%1,%2,%3};"
        : "+f"(d[0]), "+f"(d[1]), "+f"(d[2]), "+f"(d[3])
        : "r"(a[0]), "r"(a[1]), "r"(a[2]), "r"(a[3]), "r"(b[0]), "r"(b[1]));
}

// ---------------------------------------------------------------------------
// Single fused kernel: fp8 GEMM + softplus(attw) + softplus(logits) + gather
// ---------------------------------------------------------------------------
extern "C" __global__ void __launch_bounds__(NTH, 1)
cost_kernel(const float* __restrict__ logits, const float* __restrict__ attw,
            const float* __restrict__ onehot, const int* __restrict__ ids,
            float* __restrict__ out) {
    extern __shared__ __align__(16) char dynsmem[];
    uint32_t* dynw = reinterpret_cast<uint32_t*>(dynsmem);

    __shared__ alignas(8) unsigned long long bar_full[STAGES];
    __shared__ alignas(8) unsigned long long bar_empty[STAGES];
    __shared__ float s_sp[BM];  // sum_p softplus(attw[:,q])
    __shared__ float s_sa[BM];  // sum_c softplus(logits[q,:])
    __shared__ int s_ids[GG];

    const int tid = threadIdx.x;
    const int lane = tid & 31;
    const int warp = tid >> 5;
    const int q0 = blockIdx.x * BM;
    const int b = blockIdx.y;

    if (tid < BM) s_sp[tid] = 0.0f;
    if (tid == 0) {
#pragma unroll
        for (int s = 0; s < STAGES; s++) {
            MBARRIER_INIT(smem_u32(&bar_full[s]), 64);  // one producer group
            MBARRIER_INIT(smem_u32(&bar_empty[s]), 8);  // 8 consumer warps
        }
    }
    __syncthreads();

    // accumulators live in consumer warps only
    float acc[2][8][4];
    const int wm = warp >> 2;  // 0..1 (consumers)
    const int wn = warp & 3;   // 0..3
    const int g = lane >> 2;   // row-group 0..7
    const int tig = lane & 3;  // thread-in-group

    if (warp < 8) {
        // ===================== CONSUMERS (warps 0..7) ======================
#pragma unroll
        for (int i = 0; i < 2; i++)
#pragma unroll
            for (int j = 0; j < 8; j++)
#pragma unroll
                for (int k = 0; k < 4; k++) acc[i][j][k] = 0.0f;

        for (int kc = 0; kc < NKC; ++kc) {
            const int st = kc & (STAGES - 1);
            MBARRIER_WAIT_PARITY(smem_u32(&bar_full[st]), (kc >> 3) & 1);

            const uint32_t* Aw = dynw + (size_t)st * STAGE_WORDS;
            const uint32_t* Bw = Aw + A_WORDS;

            // A fragments: word[kw=tig][m], pairs (m, m+8); hi-k at kw=tig+4
            uint32_t aF[2][4];
#pragma unroll
            for (int mt = 0; mt < 2; mt++) {
                const uint32_t* plo = Aw + tig * A_ROWW + wm * 32 + mt * 16 + g;
                const uint32_t* phi = plo + 4 * A_ROWW;
                aF[mt][0] = plo[0];
                aF[mt][1] = plo[8];
                aF[mt][2] = phi[0];
                aF[mt][3] = phi[8];
            }
            // B fragments: b0=[kw=tig][n], b1=[kw=tig+4][n]
            uint32_t bF[8][2];
#pragma unroll
            for (int nt = 0; nt < 8; nt++) {
                const uint32_t* pb = Bw + tig * B_ROWW + wn * 64 + nt * 8 + g;
                bF[nt][0] = pb[0];
                bF[nt][1] = pb[4 * B_ROWW];
            }
#pragma unroll
            for (int mt = 0; mt < 2; mt++)
#pragma unroll
                for (int nt = 0; nt < 8; nt++)
                    mma_e4m3(acc[mt][nt], aF[mt], bF[nt]);

            __syncwarp();
            if (lane == 0) MBARRIER_ARRIVE(smem_u32(&bar_empty[st]));
        }
    } else {
        // ===================== PRODUCERS (warps 8..15) =====================
        // 4 groups x 64 threads; group handles kc % 4 == group.
        const int pg = tid - 256;   // 0..255
        const int group = pg >> 6;  // 0..3
        const int pt = pg & 63;     // 0..63 within group
        const int qq = pt & 15;     // A: q-quad 0..15
        const int kp = pt >> 4;     // A: kword-pair 0..3 (kwords 2kp, 2kp+1)

        const float4* aG4 =
            reinterpret_cast<const float4*>(attw + (size_t)b * PP * QQ);
        const float4* bG4 =
            reinterpret_cast<const float4*>(onehot + (size_t)b * PP * GG);
        const int q4 = q0 >> 2;

        float sp_loc[4] = {0.f, 0.f, 0.f, 0.f};

        for (int t = 0; t < NKC / 4; ++t) {
            const int kc = group + 4 * t;
            const int st = kc & (STAGES - 1);
            const int p0 = kc * BK;
            uint32_t* Aw = dynw + (size_t)st * STAGE_WORDS;
            uint32_t* Bw = Aw + A_WORDS;

            // ---- issue A loads: 8 consecutive k-rows at this q-quad ----
            float4 av[8];
#pragma unroll
            for (int i = 0; i < 8; i++)
                av[i] = aG4[(size_t)(p0 + kp * 8 + i) * (QQ / 4) + q4 + qq];
            // ---- issue B block-0 loads: rows p0..p0+7 at g-quad pt ----
            float4 bv[8];
#pragma unroll
            for (int i = 0; i < 8; i++)
                bv[i] = bG4[(size_t)(p0 + i) * (GG / 4) + pt];

            // ---- A: softplus + k-pack (in-thread, no shuffles) ----
            uint32_t aw[8];
#pragma unroll
            for (int h = 0; h < 2; h++) {
#pragma unroll
                for (int c = 0; c < 4; c++) {
                    const float f0 = (&av[4 * h + 0].x)[c];
                    const float f1 = (&av[4 * h + 1].x)[c];
                    const float f2 = (&av[4 * h + 2].x)[c];
                    const float f3 = (&av[4 * h + 3].x)[c];
                    sp_loc[c] += softplus_f(f0) + softplus_f(f1) +
                                 softplus_f(f2) + softplus_f(f3);
                    aw[4 * h + c] = pack_e4m3(f0, f1, f2, f3);
                }
            }

            // wait until consumers released this stage
            MBARRIER_WAIT_PARITY(smem_u32(&bar_empty[st]), ((kc >> 3) + 1) & 1);

            // ---- A STS: 2x STS.128, words [kw=2kp+h][q = qq*4 .. +3] ----
            {
                uint32_t a0 = smem_u32(Aw + (2 * kp + 0) * A_ROWW + qq * 4);
                STS128(a0, aw[0], aw[1], aw[2], aw[3]);
                uint32_t a1 = smem_u32(Aw + (2 * kp + 1) * A_ROWW + qq * 4);
                STS128(a1, aw[4], aw[5], aw[6], aw[7]);
            }

            // ---- B: 4 blocks of 8 rows, double-buffered loads ----
#pragma unroll
            for (int blk = 0; blk < 4; blk++) {
                float4 nb[8];
                if (blk < 3) {
#pragma unroll
                    for (int i = 0; i < 8; i++)
                        nb[i] =
                            bG4[(size_t)(p0 + 8 * (blk + 1) + i) * (GG / 4) + pt];
                }
#pragma unroll
                for (int h = 0; h < 2; h++) {
                    uint32_t w0 = pack_e4m3((&bv[4 * h + 0].x)[0],
                                            (&bv[4 * h + 1].x)[0],
                                            (&bv[4 * h + 2].x)[0],
                                            (&bv[4 * h + 3].x)[0]);
                    uint32_t w1 = pack_e4m3((&bv[4 * h + 0].x)[1],
                                            (&bv[4 * h + 1].x)[1],
                                            (&bv[4 * h + 2].x)[1],
                                            (&bv[4 * h + 3].x)[1]);
                    uint32_t w2 = pack_e4m3((&bv[4 * h + 0].x)[2],
                                            (&bv[4 * h + 1].x)[2],
                                            (&bv[4 * h + 2].x)[2],
                                            (&bv[4 * h + 3].x)[2]);
                    uint32_t w3 = pack_e4m3((&bv[4 * h + 0].x)[3],
                                            (&bv[4 * h + 1].x)[3],
                                            (&bv[4 * h + 2].x)[3],
                                            (&bv[4 * h + 3].x)[3]);
                    uint32_t dst =
                        smem_u32(Bw + (2 * blk + h) * B_ROWW + pt * 4);
                    STS128(dst, w0, w1, w2, w3);
                }
                if (blk < 3) {
#pragma unroll
                    for (int i = 0; i < 8; i++) bv[i] = nb[i];
                }
            }
            // release: arrive orders prior STS before consumers' acquire
            MBARRIER_ARRIVE(smem_u32(&bar_full[st]));
        }

        // softplus(attw) reduction: thread owns q = qq*4 + c (4 kp x 4 groups)
#pragma unroll
        for (int c = 0; c < 4; c++) atomicAdd(&s_sp[qq * 4 + c], sp_loc[c]);
    }

    // ============================ EPILOGUE =============================
    __syncthreads();  // mainloop done; ring SMEM reusable

    // stage logits fp32 (pitch 133) + ids
    {
        float* slog = reinterpret_cast<float*>(dynsmem);
        const float4* lG = reinterpret_cast<const float4*>(
            logits + (size_t)(b * QQ + q0) * CC);
#pragma unroll
        for (int i = 0; i < 4; i++) {
            int idx = tid + i * NTH;  // 0..2047 exactly covers 64x128
            float4 v = lG[idx];
            int m = idx >> 5;
            int fc = (idx & 31) * 4;
            float* dst = slog + m * L_PITCH + fc;
            dst[0] = v.x;
            dst[1] = v.y;
            dst[2] = v.z;
            dst[3] = v.w;
        }
        if (tid < GG) s_ids[tid] = ids[b * GG + tid];
    }
    __syncthreads();

    // SA: sum_c softplus(logits[m,:]) — 8 threads per row
    {
        const int row = tid >> 3;
        const int cb = tid & 7;
        const float* lr = reinterpret_cast<const float*>(dynsmem) + row * L_PITCH;
        float ss = 0.f;
#pragma unroll
        for (int k = 0; k < 16; k++) ss += softplus_f(lr[cb + 8 * k]);
        ss += __shfl_xor_sync(0xffffffffu, ss, 1);
        ss += __shfl_xor_sync(0xffffffffu, ss, 2);
        ss += __shfl_xor_sync(0xffffffffu, ss, 4);
        if (cb == 0) s_sa[row] = ss;
    }
    __syncthreads();

    if (warp < 8) {
        // output: cost = s_sp/P + s_sa/C - acc/P - gathered_logit/C
        const float inv_p = 1.0f / PP;
        const float inv_c = 1.0f / CC;
        const float* slog = reinterpret_cast<const float*>(dynsmem);
#pragma unroll
        for (int mt = 0; mt < 2; mt++) {
#pragma unroll
            for (int rr = 0; rr < 2; rr++) {
                const int m = wm * 32 + mt * 16 + g + rr * 8;
                const float Sm = s_sp[m] * inv_p + s_sa[m] * inv_c;
                float* orow = out + (size_t)(b * QQ + q0 + m) * GG;
                const float* lrow = slog + m * L_PITCH;
#pragma unroll
                for (int nt = 0; nt < 8; nt++) {
                    const int n = wn * 64 + nt * 8 + 2 * tig;
                    const float d0 = acc[mt][nt][rr * 2 + 0];
                    const float d1 = acc[mt][nt][rr * 2 + 1];
                    float2 o;
                    o.x = Sm - d0 * inv_p - lrow[s_ids[n]] * inv_c;
                    o.y = Sm - d1 * inv_p - lrow[s_ids[n + 1]] * inv_c;
                    *reinterpret_cast<float2*>(orow + n) = o;
                }
            }
        }
    }
}

// ---------------------------------------------------------------------------
extern "C" void kernel_launch(void* const* d_in, const int* in_sizes, int n_in,
                              void* d_out, int out_size) {
    const float* logits = (const float*)d_in[0];  // [B,Q,C]
    const float* attw = (const float*)d_in[1];    // [B,P,Q]
    const float* onehot = (const float*)d_in[2];  // [B,P,G]
    const int* ids = (const int*)d_in[3];         // [B,G]
    float* out = (float*)d_out;                   // [B,Q,G]

    cudaFuncSetAttribute(cost_kernel,
                         cudaFuncAttributeMaxDynamicSharedMemorySize, SMEM_DYN);

    dim3 grid(QQ / BM, BB);  // 8 x 64 = 512 CTAs
    cost_kernel<<<grid, NTH, SMEM_DYN>>>(logits, attw, onehot, ids, out);
}